// round 12
// baseline (speedup 1.0000x reference)
#include <cuda_runtime.h>
#include <cstdint>

#define B_      32
#define N_      500
#define D_      2048
#define K_      128
#define SIGMA   0.05f
#define THREADS 256          // 8 contiguous elements per thread

__device__ float g_xk[B_];    // K-th largest of x per row (or safe bin floor)
__device__ float g_xmax[B_];  // max of x per row

// monotone float -> uint (bigger float -> bigger uint)
__device__ __forceinline__ unsigned int f2u(float f) {
    unsigned int u = __float_as_uint(f);
    return u ^ (((unsigned int)((int)u >> 31)) | 0x80000000u);
}
__device__ __forceinline__ float u2f(unsigned int u) {
    unsigned int v = (u & 0x80000000u) ? (u ^ 0x80000000u) : ~u;
    return __uint_as_float(v);
}

// exclusive block scan over 256 threads (8 warps); returns total.
// Dedicated warpSums buffer per call site; no trailing barrier.
__device__ __forceinline__ unsigned int block_scan_excl(unsigned int v,
                                                        unsigned int* warpSums,
                                                        unsigned int* total) {
    const int lane = threadIdx.x & 31;
    const int wid  = threadIdx.x >> 5;
    unsigned int x = v;
    #pragma unroll
    for (int o = 1; o < 32; o <<= 1) {
        unsigned int y = __shfl_up_sync(0xffffffffu, x, o);
        if (lane >= o) x += y;
    }
    if (lane == 31) warpSums[wid] = x;
    __syncthreads();
    if (wid == 0 && lane < 8) {
        unsigned int s = warpSums[lane];
        #pragma unroll
        for (int o = 1; o < 8; o <<= 1) {
            unsigned int y = __shfl_up_sync(0xffu, s, o);
            if (lane >= o) s += y;
        }
        warpSums[lane] = s;
    }
    __syncthreads();
    unsigned int base = (wid > 0) ? warpSums[wid - 1] : 0u;
    *total = warpSums[7];
    return base + x - v;
}

// ---- prep kernel: blocks 0..31 compute xK(row) + xmax(row); blocks 32.. zero `ind` ----
#define PREP_BLOCKS 2048
__global__ __launch_bounds__(THREADS)
void prep_kernel(const float* __restrict__ x, float4* __restrict__ ind4, int n4) {
    __shared__ unsigned int hist[256];
    __shared__ unsigned int warpMaxU[8];
    __shared__ unsigned int sh_sel, sh_krem, sh_done;

    const int t = threadIdx.x;

    if (blockIdx.x >= B_) {
        if (ind4) {
            float4 z = make_float4(0.f, 0.f, 0.f, 0.f);
            int stride = (PREP_BLOCKS - B_) * THREADS;
            for (int i = (blockIdx.x - B_) * THREADS + t; i < n4; i += stride)
                ind4[i] = z;
        }
        return;
    }

    const int lane = t & 31, wid = t >> 5;
    const int b = blockIdx.x;

    unsigned int k[8];
    unsigned int mu = 0u;
    {
        const float4* xv = (const float4*)(x + (size_t)b * D_);
        float4 a = xv[2 * t], c = xv[2 * t + 1];
        k[0] = f2u(a.x); k[1] = f2u(a.y); k[2] = f2u(a.z); k[3] = f2u(a.w);
        k[4] = f2u(c.x); k[5] = f2u(c.y); k[6] = f2u(c.z); k[7] = f2u(c.w);
        #pragma unroll
        for (int i = 0; i < 8; i++) mu = max(mu, k[i]);
    }
    #pragma unroll
    for (int o = 16; o > 0; o >>= 1)
        mu = max(mu, __shfl_xor_sync(0xffffffffu, mu, o));
    if (lane == 0) warpMaxU[wid] = mu;

    unsigned int pref = 0, maskH = 0, krem = K_, done = 0;
    for (int pass = 0; pass < 4; pass++) {
        const int shift = 24 - pass * 8;
        hist[t] = 0u;
        __syncthreads();
        #pragma unroll
        for (int i = 0; i < 8; i++) {
            unsigned int kk = k[i];
            if ((kk & maskH) == pref)
                atomicAdd(&hist[(kk >> shift) & 0xFFu], 1u);
        }
        __syncthreads();
        if (wid == 0) {
            unsigned int c[8], s = 0;
            #pragma unroll
            for (int i = 0; i < 8; i++) { c[i] = hist[lane * 8 + i]; s += c[i]; }
            unsigned int xs = s;
            #pragma unroll
            for (int o = 1; o < 32; o <<= 1) {
                unsigned int y = __shfl_up_sync(0xffffffffu, xs, o);
                if (lane >= o) xs += y;
            }
            unsigned int tot = __shfl_sync(0xffffffffu, xs, 31);
            unsigned int run = xs - s;
            #pragma unroll
            for (int i = 0; i < 8; i++) {
                unsigned int sfx = tot - run, after = sfx - c[i];
                if (sfx >= krem && after < krem) {
                    sh_sel = (unsigned int)(lane * 8 + i);
                    sh_krem = krem - after;
                    sh_done = (sfx == krem);
                }
                run += c[i];
            }
        }
        __syncthreads();
        pref |= (sh_sel << shift); maskH |= (0xFFu << shift);
        krem = sh_krem; done = sh_done;
        if (done) break;
    }
    if (t == 0) {
        g_xk[b] = u2f(pref);
        unsigned int M = warpMaxU[0];
        #pragma unroll
        for (int w = 1; w < 8; w++) M = max(M, warpMaxU[w]);
        g_xmax[b] = u2f(M);
    }
}

// ---- main kernel: one CTA per (b, n) sample ----
__global__ __launch_bounds__(THREADS, 8)
void perturbed_topk_kernel(const float* __restrict__ x,
                           const float* __restrict__ noise,
                           float* __restrict__ ind,    // (B,K,D) or null
                           float* __restrict__ idxf)   // (B,N,K) or null
{
    __shared__ unsigned int   ckey[D_];
    __shared__ unsigned short cidx[D_];
    __shared__ unsigned int   hist[256];
    __shared__ unsigned int   scanA[8], scanB[8];
    __shared__ float          warpMaxN[8];
    __shared__ unsigned int   sh_sel, sh_krem, sh_done;

    const int t = threadIdx.x, lane = t & 31, wid = t >> 5;
    const int b = blockIdx.x / N_;

    // load + perturb (thread t owns elems 8t..8t+7); track max|noise|
    float kf[8];
    float am = 0.f;
    {
        const float4* xv = (const float4*)(x + (size_t)b * D_);
        const float4* nv = (const float4*)(noise + (size_t)blockIdx.x * D_);
        float4 X0 = xv[2 * t], X1 = xv[2 * t + 1];
        float4 N0 = nv[2 * t], N1 = nv[2 * t + 1];
        kf[0] = fmaf(SIGMA, N0.x, X0.x); am = fmaxf(am, fabsf(N0.x));
        kf[1] = fmaf(SIGMA, N0.y, X0.y); am = fmaxf(am, fabsf(N0.y));
        kf[2] = fmaf(SIGMA, N0.z, X0.z); am = fmaxf(am, fabsf(N0.z));
        kf[3] = fmaf(SIGMA, N0.w, X0.w); am = fmaxf(am, fabsf(N0.w));
        kf[4] = fmaf(SIGMA, N1.x, X1.x); am = fmaxf(am, fabsf(N1.x));
        kf[5] = fmaf(SIGMA, N1.y, X1.y); am = fmaxf(am, fabsf(N1.y));
        kf[6] = fmaf(SIGMA, N1.z, X1.z); am = fmaxf(am, fabsf(N1.z));
        kf[7] = fmaf(SIGMA, N1.w, X1.w); am = fmaxf(am, fabsf(N1.w));
    }
    #pragma unroll
    for (int o = 16; o > 0; o >>= 1)
        am = fmaxf(am, __shfl_xor_sync(0xffffffffu, am, o));
    if (lane == 0) warpMaxN[wid] = am;

    hist[t] = 0u;     // pre-clear first radix histogram (ordered by barrier below)
    __syncthreads();

    // every thread computes L/Lu/p0 redundantly (no 2nd barrier, no broadcast)
    float m = warpMaxN[0];
    #pragma unroll
    for (int w = 1; w < 8; w++) m = fmaxf(m, warpMaxN[w]);
    const float L = __ldg(&g_xk[b]) - SIGMA * m - 1e-4f;     // lower bnd, K-th key
    const unsigned int Lu = f2u(L);
    const unsigned int spread = f2u(__ldg(&g_xmax[b]) + SIGMA * m + 1e-4f) - Lu;
    const int p0 = (spread >> 24) ? 0 : ((spread >> 16) ? 1 : ((spread >> 8) ? 2 : 3));

    // candidate mask in float domain (f2u deferred to compaction)
    unsigned int m8 = 0;
    #pragma unroll
    for (int i = 0; i < 8; i++)
        m8 |= (kf[i] >= L) ? (1u << i) : 0u;

    unsigned int tot;
    unsigned int pos = block_scan_excl(__popc(m8), scanA, &tot);
    const int cnt = (int)tot;          // >= K guaranteed, <= 2048

    unsigned int mm = m8;
    while (mm) {
        int i = __ffs(mm) - 1;
        mm &= mm - 1;
        ckey[pos] = f2u(kf[i]) - Lu;   // rebased: order preserved, high bytes 0
        cidx[pos] = (unsigned short)(8 * t + i);
        pos++;
    }
    __syncthreads();

    // radix select over cnt rebased candidates; 2 barriers per pass
    // (warp 0 clears each hist bin right after reading it in the digit-find)
    unsigned int pref = 0;
    unsigned int maskH = (p0 > 0) ? (0xFFFFFFFFu << (32 - 8 * p0)) : 0u;
    unsigned int krem = K_, done = 0;

    for (int pass = p0; pass < 4; pass++) {
        const int shift = 24 - pass * 8;
        for (int i = t; i < cnt; i += THREADS) {
            unsigned int u = ckey[i];
            if ((u & maskH) == pref)
                atomicAdd(&hist[(u >> shift) & 0xFFu], 1u);
        }
        __syncthreads();
        if (wid == 0) {
            unsigned int c[8], s = 0;
            #pragma unroll
            for (int i = 0; i < 8; i++) {
                c[i] = hist[lane * 8 + i];
                hist[lane * 8 + i] = 0u;       // clear for next pass
                s += c[i];
            }
            unsigned int xs = s;
            #pragma unroll
            for (int o = 1; o < 32; o <<= 1) {
                unsigned int y = __shfl_up_sync(0xffffffffu, xs, o);
                if (lane >= o) xs += y;
            }
            unsigned int tt = __shfl_sync(0xffffffffu, xs, 31);
            unsigned int run = xs - s;
            #pragma unroll
            for (int i = 0; i < 8; i++) {
                unsigned int sfx = tt - run, after = sfx - c[i];
                if (sfx >= krem && after < krem) {
                    sh_sel = (unsigned int)(lane * 8 + i);
                    sh_krem = krem - after;
                    sh_done = (sfx == krem);
                }
                run += c[i];
            }
        }
        __syncthreads();
        pref |= (sh_sel << shift); maskH |= (0xFFu << shift);
        krem = sh_krem; done = sh_done;
        if (done) break;           // uniform
    }
    const unsigned int T = pref;        // threshold in rebased domain
    const unsigned int R = done ? (unsigned int)K_ : krem;

    // contiguous-chunk ownership keeps array (= index) order for the rank scan
    const int ept = (cnt + THREADS - 1) / THREADS;   // usually 1
    const int beg = t * ept;
    int end = beg + ept; if (end > cnt) end = cnt;

    unsigned int gt = 0, eq = 0;
    for (int i = beg; i < end; i++) {
        unsigned int u = ckey[i];
        gt += (u > T);
        eq += (u == T);
    }
    unsigned int tot2;
    unsigned int pr = block_scan_excl(gt | (eq << 16), scanB, &tot2);
    unsigned int gtB = pr & 0xFFFFu;
    unsigned int eqB = pr >> 16;

    unsigned int j = gtB + ((eqB < R) ? eqB : R);
    unsigned int eqRank = eqB;
    const size_t idxBase = (size_t)blockIdx.x * K_;
    float* __restrict__ indRow = ind ? (ind + (size_t)b * K_ * D_) : nullptr;
    const float inv_n = 1.0f / (float)N_;

    for (int i = beg; i < end; i++) {
        unsigned int u = ckey[i];
        bool isEq = (u == T);
        bool sel  = (u > T) || (isEq && (eqRank < R));
        eqRank += isEq ? 1u : 0u;
        if (sel) {
            int e = (int)cidx[i];
            if (idxf) idxf[idxBase + j] = (float)e;
            if (indRow) atomicAdd(indRow + (size_t)j * D_ + e, inv_n);
            j++;
        }
    }
}

extern "C" void kernel_launch(void* const* d_in, const int* in_sizes, int n_in,
                              void* d_out, int out_size) {
    const float* x     = (const float*)d_in[0];
    const float* noise = (const float*)d_in[1];
    if (n_in >= 2 && in_sizes[0] != B_ * D_) {
        x     = (const float*)d_in[1];
        noise = (const float*)d_in[0];
    }

    const long long IND = (long long)B_ * K_ * D_;   // 8388608
    const long long IDX = (long long)B_ * N_ * K_;   // 2048000

    float* ind  = nullptr;
    float* idxf = nullptr;
    if ((long long)out_size >= IND + IDX) {
        ind  = (float*)d_out;
        idxf = (float*)d_out + IND;
    } else if ((long long)out_size == IND) {
        ind = (float*)d_out;
    } else if ((long long)out_size == IDX) {
        idxf = (float*)d_out;
    } else {
        ind = (float*)d_out;
    }

    prep_kernel<<<PREP_BLOCKS, THREADS>>>(x, (float4*)ind, (int)(IND / 4));
    perturbed_topk_kernel<<<B_ * N_, THREADS>>>(x, noise, ind, idxf);
}

// round 13
// speedup vs baseline: 1.1234x; 1.1234x over previous
#include <cuda_runtime.h>
#include <cstdint>

#define B_      32
#define N_      500
#define D_      2048
#define K_      128
#define SIGMA   0.05f
#define THREADS 256
#define CAP     0.35f        // 7-sigma noise cap; violations caught via T==0 fallback

__device__ uint2        g_cand[B_][D_];  // per-row candidates: {x float bits, index}
__device__ int          g_cnt[B_];
__device__ unsigned int g_Lu[B_];        // f2u(xK - CAP - eps): rebase base
__device__ unsigned int g_Mu[B_];        // f2u(xmax + CAP + eps): upper bound

// monotone float -> uint (bigger float -> bigger uint)
__device__ __forceinline__ unsigned int f2u(float f) {
    unsigned int u = __float_as_uint(f);
    return u ^ (((unsigned int)((int)u >> 31)) | 0x80000000u);
}
__device__ __forceinline__ float u2f(unsigned int u) {
    unsigned int v = (u & 0x80000000u) ? (u ^ 0x80000000u) : ~u;
    return __uint_as_float(v);
}

// exclusive block scan over 256 threads (8 warps); returns total.
__device__ __forceinline__ unsigned int block_scan_excl(unsigned int v,
                                                        unsigned int* warpSums,
                                                        unsigned int* total) {
    const int lane = threadIdx.x & 31;
    const int wid  = threadIdx.x >> 5;
    unsigned int x = v;
    #pragma unroll
    for (int o = 1; o < 32; o <<= 1) {
        unsigned int y = __shfl_up_sync(0xffffffffu, x, o);
        if (lane >= o) x += y;
    }
    if (lane == 31) warpSums[wid] = x;
    __syncthreads();
    if (wid == 0 && lane < 8) {
        unsigned int s = warpSums[lane];
        #pragma unroll
        for (int o = 1; o < 8; o <<= 1) {
            unsigned int y = __shfl_up_sync(0xffu, s, o);
            if (lane >= o) s += y;
        }
        warpSums[lane] = s;
    }
    __syncthreads();
    unsigned int base = (wid > 0) ? warpSums[wid - 1] : 0u;
    *total = warpSums[7];
    return base + x - v;
}

// ---- prep: blocks 0..31 -> xK, xmax, candidate list per row; rest zero `ind` ----
#define PREP_BLOCKS 2048
__global__ __launch_bounds__(THREADS)
void prep_kernel(const float* __restrict__ x, float4* __restrict__ ind4, int n4) {
    __shared__ unsigned int hist[256];
    __shared__ unsigned int warpMaxU[8];
    __shared__ unsigned int sh_sel, sh_krem, sh_done;

    const int t = threadIdx.x;

    if (blockIdx.x >= B_) {
        if (ind4) {
            float4 z = make_float4(0.f, 0.f, 0.f, 0.f);
            int stride = (PREP_BLOCKS - B_) * THREADS;
            for (int i = (blockIdx.x - B_) * THREADS + t; i < n4; i += stride)
                ind4[i] = z;
        }
        return;
    }

    const int lane = t & 31, wid = t >> 5;
    const int b = blockIdx.x;

    unsigned int k[8];
    unsigned int mu = 0u;
    {
        const float4* xv = (const float4*)(x + (size_t)b * D_);
        float4 a = xv[2 * t], c = xv[2 * t + 1];
        k[0] = f2u(a.x); k[1] = f2u(a.y); k[2] = f2u(a.z); k[3] = f2u(a.w);
        k[4] = f2u(c.x); k[5] = f2u(c.y); k[6] = f2u(c.z); k[7] = f2u(c.w);
        #pragma unroll
        for (int i = 0; i < 8; i++) mu = max(mu, k[i]);
    }
    #pragma unroll
    for (int o = 16; o > 0; o >>= 1)
        mu = max(mu, __shfl_xor_sync(0xffffffffu, mu, o));
    if (lane == 0) warpMaxU[wid] = mu;

    // radix select: K-th largest of x (early-exit -> bin floor, still a valid LB)
    unsigned int pref = 0, maskH = 0, krem = K_, done = 0;
    for (int pass = 0; pass < 4; pass++) {
        const int shift = 24 - pass * 8;
        hist[t] = 0u;
        __syncthreads();
        #pragma unroll
        for (int i = 0; i < 8; i++) {
            unsigned int kk = k[i];
            if ((kk & maskH) == pref)
                atomicAdd(&hist[(kk >> shift) & 0xFFu], 1u);
        }
        __syncthreads();
        if (wid == 0) {
            unsigned int c[8], s = 0;
            #pragma unroll
            for (int i = 0; i < 8; i++) { c[i] = hist[lane * 8 + i]; s += c[i]; }
            unsigned int xs = s;
            #pragma unroll
            for (int o = 1; o < 32; o <<= 1) {
                unsigned int y = __shfl_up_sync(0xffffffffu, xs, o);
                if (lane >= o) xs += y;
            }
            unsigned int tot = __shfl_sync(0xffffffffu, xs, 31);
            unsigned int run = xs - s;
            #pragma unroll
            for (int i = 0; i < 8; i++) {
                unsigned int sfx = tot - run, after = sfx - c[i];
                if (sfx >= krem && after < krem) {
                    sh_sel = (unsigned int)(lane * 8 + i);
                    sh_krem = krem - after;
                    sh_done = (sfx == krem);
                }
                run += c[i];
            }
        }
        __syncthreads();
        pref |= (sh_sel << shift); maskH |= (0xFFu << shift);
        krem = sh_krem; done = sh_done;
        if (done) break;
    }

    // candidate compaction: x_e >= xk - 2*CAP (ascending index order)
    const float xk = u2f(pref);                         // (LB of) K-th largest
    const unsigned int Fu = f2u(xk - 2.0f * CAP - 1e-4f);
    unsigned int m8 = 0;
    #pragma unroll
    for (int i = 0; i < 8; i++)
        m8 |= (k[i] >= Fu) ? (1u << i) : 0u;

    unsigned int tot;
    unsigned int pos = block_scan_excl(__popc(m8), hist, &tot);  // hist reused

    unsigned int mm = m8;
    while (mm) {
        int i = __ffs(mm) - 1;
        mm &= mm - 1;
        g_cand[b][pos] = make_uint2(__float_as_uint(u2f(k[i])),
                                    (unsigned int)(8 * t + i));
        pos++;
    }
    if (t == 0) {
        g_cnt[b] = (int)tot;                            // >= K by construction
        g_Lu[b]  = f2u(xk - CAP - 1e-4f);
        unsigned int M = warpMaxU[0];
        #pragma unroll
        for (int w = 1; w < 8; w++) M = max(M, warpMaxU[w]);
        g_Mu[b]  = f2u(u2f(M) + CAP + 1e-4f);
    }
}

// ---- main kernel: one CTA per (b, n); only candidates processed ----
__global__ __launch_bounds__(THREADS, 8)
void perturbed_topk_kernel(const float* __restrict__ noise,
                           float* __restrict__ ind,    // (B,K,D) or null
                           float* __restrict__ idxf)   // (B,N,K) or null
{
    __shared__ unsigned int   ckey[D_];
    __shared__ unsigned short cidx[D_];
    __shared__ unsigned int   hist[256];
    __shared__ unsigned int   scanB[8];
    __shared__ unsigned int   sh_sel, sh_krem, sh_done;

    const int t = threadIdx.x, lane = t & 31, wid = t >> 5;
    const int b = blockIdx.x / N_;

    const float* __restrict__ nrow = noise + (size_t)blockIdx.x * D_;
    const uint2* __restrict__ cand = g_cand[b];
    const int cb = g_cnt[b];                 // ~420, >= K
    const unsigned int Lu = g_Lu[b];
    const unsigned int spread = g_Mu[b] - Lu;
    int p0 = (spread >> 24) ? 0 : ((spread >> 16) ? 1 : ((spread >> 8) ? 2 : 3));

    // gather + perturb only at candidate positions; rebase with clamp
    for (int i = t; i < cb; i += THREADS) {
        uint2 c = cand[i];
        float kf = fmaf(SIGMA, __ldg(nrow + c.y), __uint_as_float(c.x));
        unsigned int u = f2u(kf);
        ckey[i] = (u > Lu) ? (u - Lu) : 0u;  // clamp: keys <= L can't be top-K
        cidx[i] = (unsigned short)c.y;
    }
    // (first radix barrier below orders these writes)

    unsigned int T, R;
    for (int attempt = 0; ; attempt++) {
        unsigned int pref = 0;
        unsigned int maskH = (p0 > 0) ? (0xFFFFFFFFu << (32 - 8 * p0)) : 0u;
        unsigned int krem = K_, done = 0;

        for (int pass = p0; pass < 4; pass++) {
            const int shift = 24 - pass * 8;
            hist[t] = 0u;
            __syncthreads();
            for (int i = t; i < cb; i += THREADS) {
                unsigned int u = ckey[i];
                if ((u & maskH) == pref)
                    atomicAdd(&hist[(u >> shift) & 0xFFu], 1u);
            }
            __syncthreads();
            if (wid == 0) {
                unsigned int c[8], s = 0;
                #pragma unroll
                for (int i = 0; i < 8; i++) { c[i] = hist[lane * 8 + i]; s += c[i]; }
                unsigned int xs = s;
                #pragma unroll
                for (int o = 1; o < 32; o <<= 1) {
                    unsigned int y = __shfl_up_sync(0xffffffffu, xs, o);
                    if (lane >= o) xs += y;
                }
                unsigned int tt = __shfl_sync(0xffffffffu, xs, 31);
                unsigned int run = xs - s;
                #pragma unroll
                for (int i = 0; i < 8; i++) {
                    unsigned int sfx = tt - run, after = sfx - c[i];
                    if (sfx >= krem && after < krem) {
                        sh_sel = (unsigned int)(lane * 8 + i);
                        sh_krem = krem - after;
                        sh_done = (sfx == krem);
                    }
                    run += c[i];
                }
            }
            __syncthreads();
            pref |= (sh_sel << shift); maskH |= (0xFFu << shift);
            krem = sh_krem; done = sh_done;
            if (done) break;          // uniform
        }
        T = pref;
        R = done ? (unsigned int)K_ : krem;
        if (T != 0u || attempt == 1) break;

        // T==0: noise cap violated or degenerate tie at clamp level.
        // Exact fallback: raw (unclamped, unrebased) keys, full 4-pass radix.
        for (int i = t; i < cb; i += THREADS) {
            uint2 c = cand[i];
            ckey[i] = f2u(fmaf(SIGMA, __ldg(nrow + c.y), __uint_as_float(c.x)));
        }
        p0 = 0;
        __syncthreads();
    }

    // contiguous-chunk ownership keeps array (= ascending index) order
    const int ept = (cb + THREADS - 1) / THREADS;   // usually 2
    const int beg = t * ept;
    int end = beg + ept; if (end > cb) end = cb;

    unsigned int gt = 0, eq = 0;
    for (int i = beg; i < end; i++) {
        unsigned int u = ckey[i];
        gt += (u > T);
        eq += (u == T);
    }
    unsigned int tot2;
    unsigned int pr = block_scan_excl(gt | (eq << 16), scanB, &tot2);
    unsigned int gtB = pr & 0xFFFFu;
    unsigned int eqB = pr >> 16;

    unsigned int j = gtB + ((eqB < R) ? eqB : R);
    unsigned int eqRank = eqB;
    const size_t idxBase = (size_t)blockIdx.x * K_;
    float* __restrict__ indRow = ind ? (ind + (size_t)b * K_ * D_) : nullptr;
    const float inv_n = 1.0f / (float)N_;

    for (int i = beg; i < end; i++) {
        unsigned int u = ckey[i];
        bool isEq = (u == T);
        bool sel  = (u > T) || (isEq && (eqRank < R));
        eqRank += isEq ? 1u : 0u;
        if (sel) {
            int e = (int)cidx[i];
            if (idxf) idxf[idxBase + j] = (float)e;
            if (indRow) atomicAdd(indRow + (size_t)j * D_ + e, inv_n);
            j++;
        }
    }
}

extern "C" void kernel_launch(void* const* d_in, const int* in_sizes, int n_in,
                              void* d_out, int out_size) {
    const float* x     = (const float*)d_in[0];
    const float* noise = (const float*)d_in[1];
    if (n_in >= 2 && in_sizes[0] != B_ * D_) {
        x     = (const float*)d_in[1];
        noise = (const float*)d_in[0];
    }

    const long long IND = (long long)B_ * K_ * D_;   // 8388608
    const long long IDX = (long long)B_ * N_ * K_;   // 2048000

    float* ind  = nullptr;
    float* idxf = nullptr;
    if ((long long)out_size >= IND + IDX) {
        ind  = (float*)d_out;
        idxf = (float*)d_out + IND;
    } else if ((long long)out_size == IND) {
        ind = (float*)d_out;
    } else if ((long long)out_size == IDX) {
        idxf = (float*)d_out;
    } else {
        ind = (float*)d_out;
    }

    prep_kernel<<<PREP_BLOCKS, THREADS>>>(x, (float4*)ind, (int)(IND / 4));
    perturbed_topk_kernel<<<B_ * N_, THREADS>>>(noise, ind, idxf);
}